// round 6
// baseline (speedup 1.0000x reference)
#include <cuda_runtime.h>
#include <cstdint>

// B=4096 poses x N=4096 points, pure HBM streaming reduction (201 MB).
// R6 (fixed R5): one CTA (1 warp) = one (pose, segment) of 1024 points
// (= 256 float4-groups = 12 KB). SEGS=4 -> 16384 CTAs, dynamically scheduled
// so per-SM load self-balances and the drain tail is one segment.
// Per-pose partials combine via atomicAdd scratch; the last-arriving segment
// finalizes out[b] and resets the scratch (deterministic across graph replays).

#define NPTS 4096
#define SEGS 4
#define GROUPS_PER_SEG 256          // 1024 points / 4 per group
#define CHUNKS_PER_LANE 8           // 256 groups / 32 lanes
#define MAXB 4096

__device__ float g_psum[MAXB];      // zero-init at load; finalizer resets each run
__device__ int   g_pcnt[MAXB];
__device__ int   g_done[MAXB];

__device__ __forceinline__ void process4(
    const float4 A, const float4 Bv, const float4 C,
    const float r00, const float r01, const float r02,
    const float r10, const float r11, const float r12,
    const float r20, const float r21, const float r22,
    const float trx, const float try_, const float trz,
    float& sum, int& cnt)
{
    // AABB bounds (identical double->float rounding to the numpy reference)
    const float lox = (float)(-0.001782 - (0.204416 / 2.0 + 0.001));
    const float hix = (float)(-0.001782 + (0.204416 / 2.0 + 0.001));
    const float loy = (float)(1.005e-05 - (0.0632517 / 2.0 + 0.001));
    const float hiy = (float)(1.005e-05 + (0.0632517 / 2.0 + 0.001));
    const float loz = (float)(0.0431621 - (0.1381738 / 2.0 + 0.001));
    const float hiz = (float)(0.0431621 + (0.1381738 / 2.0 + 0.001));

    const float px[4] = {A.x, A.w, Bv.z, C.y};
    const float py[4] = {A.y, Bv.x, Bv.w, C.z};
    const float pz[4] = {A.z, Bv.y, C.x, C.w};
#pragma unroll
    for (int k = 0; k < 4; ++k) {
        const float x = px[k], y = py[k], z = pz[k];
        const float rx = fmaf(r00, x, fmaf(r01, y, fmaf(r02, z, -trx)));
        const float ry = fmaf(r10, x, fmaf(r11, y, fmaf(r12, z, -try_)));
        const float rz = fmaf(r20, x, fmaf(r21, y, fmaf(r22, z, -trz)));
        const bool inside =
            (rx >= lox) & (rx <= hix) &
            (ry >= loy) & (ry <= hiy) &
            (rz >= loz) & (rz <= hiz);
        const float nrm = sqrtf(fmaf(rx, rx, fmaf(ry, ry, rz * rz)));
        sum += inside ? nrm : 0.0f;
        cnt += (int)inside;
    }
}

__global__ __launch_bounds__(32) void collision_dist_kernel(
    const float* __restrict__ trans,   // [B,3]
    const float* __restrict__ quat,    // [B,4]
    const float* __restrict__ pc,      // [B,N,3]
    float* __restrict__ out)           // [B,1]
{
    const int lane = threadIdx.x;
    const int b    = blockIdx.x >> 2;        // pose
    const int seg  = blockIdx.x & (SEGS - 1);

    // ---- per-pose setup (28 B, L1/L2-resident; redundant across segments) ----
    const float qx = __ldg(&quat[b * 4 + 0]);
    const float qy = __ldg(&quat[b * 4 + 1]);
    const float qz = __ldg(&quat[b * 4 + 2]);
    const float qw = __ldg(&quat[b * 4 + 3]);
    const float inv = 1.0f / (qx * qx + qy * qy + qz * qz + qw * qw);
    const float tx = -qx * inv, ty = -qy * inv, tz = -qz * inv, tw = qw * inv;

    const float txx = tx * tx, tyy = ty * ty, tzz = tz * tz, tww = tw * tw;
    const float r00 = tww + txx - tyy - tzz;
    const float r11 = tww - txx + tyy - tzz;
    const float r22 = tww - txx - tyy + tzz;
    const float r01 = 2.0f * (tx * ty - tw * tz);
    const float r02 = 2.0f * (tx * tz + tw * ty);
    const float r10 = 2.0f * (tx * ty + tw * tz);
    const float r12 = 2.0f * (ty * tz - tw * tx);
    const float r20 = 2.0f * (tx * tz - tw * ty);
    const float r21 = 2.0f * (ty * tz + tw * tx);

    const float trx  = __ldg(&trans[b * 3 + 0]);
    const float try_ = __ldg(&trans[b * 3 + 1]);
    const float trz  = __ldg(&trans[b * 3 + 2]);

    const float4* __restrict__ row =
        reinterpret_cast<const float4*>(pc + (size_t)b * (size_t)NPTS * 3);
    const int gbase = seg * GROUPS_PER_SEG;  // first float4-group of segment

    // ---- stream 1024 points: 8 chunks/lane, distance-2 prefetch pipeline ----
    float sum = 0.0f;
    int   cnt = 0;

    float4 buf[2][3];
    {
        const float4* p0 = row + (size_t)(gbase + lane) * 3;
        const float4* p1 = row + (size_t)(gbase + lane + 32) * 3;
        buf[0][0] = __ldcs(p0 + 0); buf[0][1] = __ldcs(p0 + 1); buf[0][2] = __ldcs(p0 + 2);
        buf[1][0] = __ldcs(p1 + 0); buf[1][1] = __ldcs(p1 + 1); buf[1][2] = __ldcs(p1 + 2);
    }

#pragma unroll
    for (int j = 0; j < CHUNKS_PER_LANE - 2; ++j) {
        const float4 A  = buf[j & 1][0];
        const float4 Bv = buf[j & 1][1];
        const float4 C  = buf[j & 1][2];
        const float4* q = row + (size_t)(gbase + lane + 32 * (j + 2)) * 3;
        buf[j & 1][0] = __ldcs(q + 0);
        buf[j & 1][1] = __ldcs(q + 1);
        buf[j & 1][2] = __ldcs(q + 2);
        process4(A, Bv, C, r00, r01, r02, r10, r11, r12, r20, r21, r22,
                 trx, try_, trz, sum, cnt);
    }
    process4(buf[0][0], buf[0][1], buf[0][2], r00, r01, r02, r10, r11, r12,
             r20, r21, r22, trx, try_, trz, sum, cnt);
    process4(buf[1][0], buf[1][1], buf[1][2], r00, r01, r02, r10, r11, r12,
             r20, r21, r22, trx, try_, trz, sum, cnt);

    // ---- warp reduction ----
#pragma unroll
    for (int off = 16; off > 0; off >>= 1) {
        sum += __shfl_down_sync(0xFFFFFFFFu, sum, off);
        cnt += __shfl_down_sync(0xFFFFFFFFu, cnt, off);
    }

    // ---- combine across segments; last arriver finalizes + resets ----
    if (lane == 0) {
        atomicAdd(&g_psum[b], sum);
        atomicAdd(&g_pcnt[b], cnt);
        __threadfence();                        // release partials before done++
        const int prior = atomicAdd(&g_done[b], 1);
        if (prior == SEGS - 1) {                // last segment for this pose
            __threadfence();                    // acquire all partials
            const float tot_s = atomicAdd(&g_psum[b], 0.0f);
            const int   tot_c = atomicAdd(&g_pcnt[b], 0);
            const float dist = (tot_c > 0) ? (-tot_s / (float)max(tot_c, 1)) : 1.0f;
            out[b] = dist * 10000.0f;
            // reset scratch for the next graph replay (replays are serialized)
            atomicExch(&g_psum[b], 0.0f);
            atomicExch(&g_pcnt[b], 0);
            __threadfence();
            atomicExch(&g_done[b], 0);
        }
    }
}

extern "C" void kernel_launch(void* const* d_in, const int* in_sizes, int n_in,
                              void* d_out, int out_size)
{
    const float* trans = (const float*)d_in[0];  // [4096,3]
    const float* quat  = (const float*)d_in[1];  // [4096,4]
    const float* pc    = (const float*)d_in[2];  // [4096,4096,3]
    float* out = (float*)d_out;                  // [4096,1]

    const int B = in_sizes[0] / 3;               // 4096 poses
    collision_dist_kernel<<<B * SEGS, 32>>>(trans, quat, pc, out);
}

// round 7
// speedup vs baseline: 1.0725x; 1.0725x over previous
#include <cuda_runtime.h>
#include <cstdint>

// B=4096 poses x N=4096 points, pure HBM streaming reduction (201 MB).
// R7: back to warp-per-pose (R4 skeleton, best so far), with a DISTANCE-3
// prefetch ring: 9 float4 loads (4.5 KB) in flight per warp for the whole
// 48 KB row lifetime. 4096 one-warp CTAs = single wave, no barriers/atomics.

#define NPTS 4096

__device__ __forceinline__ void process4(
    const float4 A, const float4 Bv, const float4 C,
    const float r00, const float r01, const float r02,
    const float r10, const float r11, const float r12,
    const float r20, const float r21, const float r22,
    const float trx, const float try_, const float trz,
    float& sum, int& cnt)
{
    // AABB bounds (identical double->float rounding to the numpy reference)
    const float lox = (float)(-0.001782 - (0.204416 / 2.0 + 0.001));
    const float hix = (float)(-0.001782 + (0.204416 / 2.0 + 0.001));
    const float loy = (float)(1.005e-05 - (0.0632517 / 2.0 + 0.001));
    const float hiy = (float)(1.005e-05 + (0.0632517 / 2.0 + 0.001));
    const float loz = (float)(0.0431621 - (0.1381738 / 2.0 + 0.001));
    const float hiz = (float)(0.0431621 + (0.1381738 / 2.0 + 0.001));

    const float px[4] = {A.x, A.w, Bv.z, C.y};
    const float py[4] = {A.y, Bv.x, Bv.w, C.z};
    const float pz[4] = {A.z, Bv.y, C.x, C.w};
#pragma unroll
    for (int k = 0; k < 4; ++k) {
        const float x = px[k], y = py[k], z = pz[k];
        const float rx = fmaf(r00, x, fmaf(r01, y, fmaf(r02, z, -trx)));
        const float ry = fmaf(r10, x, fmaf(r11, y, fmaf(r12, z, -try_)));
        const float rz = fmaf(r20, x, fmaf(r21, y, fmaf(r22, z, -trz)));
        const bool inside =
            (rx >= lox) & (rx <= hix) &
            (ry >= loy) & (ry <= hiy) &
            (rz >= loz) & (rz <= hiz);
        const float nrm = sqrtf(fmaf(rx, rx, fmaf(ry, ry, rz * rz)));
        sum += inside ? nrm : 0.0f;
        cnt += (int)inside;
    }
}

__global__ __launch_bounds__(32, 26) void collision_dist_kernel(
    const float* __restrict__ trans,   // [B,3]
    const float* __restrict__ quat,    // [B,4]
    const float* __restrict__ pc,      // [B,N,3]
    float* __restrict__ out)           // [B,1]
{
    const int lane = threadIdx.x;
    const int b    = blockIdx.x;       // one pose per warp/CTA

    const float4* __restrict__ row =
        reinterpret_cast<const float4*>(pc + (size_t)b * (size_t)NPTS * 3);

    // ---- prologue: issue 3 chunks (9 float4) before any dependent math ----
    float4 buf[3][3];
#pragma unroll
    for (int s = 0; s < 3; ++s) {
        const float4* p = row + (size_t)(lane + 32 * s) * 3;
        buf[s][0] = __ldcs(p + 0);
        buf[s][1] = __ldcs(p + 1);
        buf[s][2] = __ldcs(p + 2);
    }

    // ---- per-pose setup overlaps with the first loads in flight ----
    const float qx = __ldg(&quat[b * 4 + 0]);
    const float qy = __ldg(&quat[b * 4 + 1]);
    const float qz = __ldg(&quat[b * 4 + 2]);
    const float qw = __ldg(&quat[b * 4 + 3]);
    const float inv = 1.0f / (qx * qx + qy * qy + qz * qz + qw * qw);
    const float tx = -qx * inv, ty = -qy * inv, tz = -qz * inv, tw = qw * inv;

    const float txx = tx * tx, tyy = ty * ty, tzz = tz * tz, tww = tw * tw;
    const float r00 = tww + txx - tyy - tzz;
    const float r11 = tww - txx + tyy - tzz;
    const float r22 = tww - txx - tyy + tzz;
    const float r01 = 2.0f * (tx * ty - tw * tz);
    const float r02 = 2.0f * (tx * tz + tw * ty);
    const float r10 = 2.0f * (tx * ty + tw * tz);
    const float r12 = 2.0f * (ty * tz - tw * tx);
    const float r20 = 2.0f * (tx * tz - tw * ty);
    const float r21 = 2.0f * (ty * tz + tw * tx);

    const float trx  = __ldg(&trans[b * 3 + 0]);
    const float try_ = __ldg(&trans[b * 3 + 1]);
    const float trz  = __ldg(&trans[b * 3 + 2]);

    // ---- steady state: 32 chunks/lane, distance-3 ring ----
    float sum = 0.0f;
    int   cnt = 0;

#pragma unroll 3
    for (int j = 0; j < 29; ++j) {
        const int slot = j % 3;
        const float4 A  = buf[slot][0];
        const float4 Bv = buf[slot][1];
        const float4 C  = buf[slot][2];
        const float4* q = row + (size_t)(lane + 32 * (j + 3)) * 3;
        buf[slot][0] = __ldcs(q + 0);
        buf[slot][1] = __ldcs(q + 1);
        buf[slot][2] = __ldcs(q + 2);
        process4(A, Bv, C, r00, r01, r02, r10, r11, r12, r20, r21, r22,
                 trx, try_, trz, sum, cnt);
    }
#pragma unroll
    for (int j = 29; j < 32; ++j) {
        const int slot = j % 3;
        process4(buf[slot][0], buf[slot][1], buf[slot][2],
                 r00, r01, r02, r10, r11, r12, r20, r21, r22,
                 trx, try_, trz, sum, cnt);
    }

    // ---- warp reduction (no smem, no barriers) ----
#pragma unroll
    for (int off = 16; off > 0; off >>= 1) {
        sum += __shfl_down_sync(0xFFFFFFFFu, sum, off);
        cnt += __shfl_down_sync(0xFFFFFFFFu, cnt, off);
    }
    if (lane == 0) {
        const float dist = (cnt > 0) ? (-sum / (float)max(cnt, 1)) : 1.0f;
        out[b] = dist * 10000.0f;
    }
}

extern "C" void kernel_launch(void* const* d_in, const int* in_sizes, int n_in,
                              void* d_out, int out_size)
{
    const float* trans = (const float*)d_in[0];  // [4096,3]
    const float* quat  = (const float*)d_in[1];  // [4096,4]
    const float* pc    = (const float*)d_in[2];  // [4096,4096,3]
    float* out = (float*)d_out;                  // [4096,1]

    const int B = in_sizes[0] / 3;               // 4096 poses
    collision_dist_kernel<<<B, 32>>>(trans, quat, pc, out);
}